// round 2
// baseline (speedup 1.0000x reference)
#include <cuda_runtime.h>
#include <cstdint>

// Scratch (no cudaMalloc allowed): exp(transitions) packed per-lane, per-batch losses.
__device__ float2 g_Mpack[64 * 32];   // g_Mpack[i*32+l] = (exp(T[i][l]), exp(T[i][l+32]))
__device__ float  g_loss[4096];

// ---------- f32x2 packed math (sm_10x; ptxas won't auto-fuse these) ----------
static __device__ __forceinline__ unsigned long long pack2f(float lo, float hi) {
    unsigned long long r;
    asm("mov.b64 %0, {%1, %2};" : "=l"(r) : "f"(lo), "f"(hi));
    return r;
}
static __device__ __forceinline__ void unpack2f(unsigned long long v, float& lo, float& hi) {
    asm("mov.b64 {%0, %1}, %2;" : "=f"(lo), "=f"(hi) : "l"(v));
}
static __device__ __forceinline__ unsigned long long ffma2(unsigned long long a,
                                                           unsigned long long b,
                                                           unsigned long long c) {
    unsigned long long d;
    asm("fma.rn.f32x2 %0, %1, %2, %3;" : "=l"(d) : "l"(a), "l"(b), "l"(c));
    return d;
}
static __device__ __forceinline__ unsigned long long fadd2(unsigned long long a,
                                                           unsigned long long b) {
    unsigned long long d;
    asm("add.rn.f32x2 %0, %1, %2;" : "=l"(d) : "l"(a), "l"(b));
    return d;
}
static __device__ __forceinline__ unsigned long long fmul2(unsigned long long a,
                                                           unsigned long long b) {
    unsigned long long d;
    asm("mul.rn.f32x2 %0, %1, %2;" : "=l"(d) : "l"(a), "l"(b));
    return d;
}

// ---------- kernel 0: M = exp(transitions), packed for lane-column access ----------
__global__ void __launch_bounds__(128) crf_precompute(const float* __restrict__ trans) {
    int idx = blockIdx.x * blockDim.x + threadIdx.x;
    if (idx < 64 * 32) {
        int i = idx >> 5, l = idx & 31;
        // rows 62,63 are exactly -10000 -> __expf underflows to 0.f (harmless; alpha there is 0)
        g_Mpack[idx] = make_float2(__expf(trans[i * 64 + l]),
                                   __expf(trans[i * 64 + l + 32]));
    }
}

// ---------- kernel 1: one warp per batch row, exp-space forward + gold score ----------
__global__ void __launch_bounds__(32) crf_forward(
    const float* __restrict__ pred,     // [B, T, 62]
    const int*   __restrict__ ref,      // [B, T]
    const int*   __restrict__ seq_len,  // [B]
    const float* __restrict__ trans,    // [64, 64] (raw, for gold score)
    int B, int T)
{
    const int b = blockIdx.x;
    if (b >= B) return;
    const int lane = threadIdx.x;

    __shared__ __align__(16) float alphaS[64];

    // M columns (lane, lane+32) in registers: 64 x f32x2 = 128 regs
    unsigned long long Mreg[64];
#pragma unroll
    for (int i = 0; i < 64; i++)
        Mreg[i] = *reinterpret_cast<const unsigned long long*>(&g_Mpack[i * 32 + lane]);

    // end-transition factors Tend[i] = exp(trans[i][63])
    const float T_lo = g_Mpack[lane * 32 + 31].y;
    const float T_hi = g_Mpack[(lane + 32) * 32 + 31].y;

    const int S = seq_len[b];                         // in [1, T]
    const float* prow = pred + (size_t)b * T * 62;

    // init: alpha0 = ones over the 62 labels (b_s floor -1000 factored into C)
    alphaS[lane]      = 1.0f;
    alphaS[lane + 32] = (lane < 30) ? 1.0f : 0.0f;
    __syncwarp();

    float C     = -1000.0f;
    float inv_s = 1.0f / 62.0f;
    float pend  = __logf(62.0f);                      // log s_{t-1}, added lazily

    // prefetch emission row for t=1
    float p_lo = prow[lane];
    float p_hi = (lane < 30) ? prow[lane + 32] : 0.0f;

    float v_lo = 0.0f, v_hi = 0.0f;

    for (int t = 1; t <= S; t++) {
        // emission * (1/s_prev) folded together
        float e_lo = __expf(p_lo) * inv_s;
        float e_hi = (lane < 30) ? __expf(p_hi) * inv_s : 0.0f;

        // prefetch next emission row
        if (t < S) {
            const float* nr = prow + (size_t)t * 62;
            p_lo = nr[lane];
            if (lane < 30) p_hi = nr[lane + 32];
        }

        // matvec: acc[j] = sum_i alpha[i] * M[i][j], 4 accumulators for ILP
        unsigned long long acc0 = 0ull, acc1 = 0ull, acc2 = 0ull, acc3 = 0ull;
#pragma unroll
        for (int i = 0; i < 64; i += 4) {
            float4 a = *reinterpret_cast<const float4*>(&alphaS[i]);  // broadcast LDS.128
            acc0 = ffma2(pack2f(a.x, a.x), Mreg[i + 0], acc0);
            acc1 = ffma2(pack2f(a.y, a.y), Mreg[i + 1], acc1);
            acc2 = ffma2(pack2f(a.z, a.z), Mreg[i + 2], acc2);
            acc3 = ffma2(pack2f(a.w, a.w), Mreg[i + 3], acc3);
        }
        unsigned long long acc = fadd2(fadd2(acc0, acc1), fadd2(acc2, acc3));
        unsigned long long v2  = fmul2(acc, pack2f(e_lo, e_hi));
        unpack2f(v2, v_lo, v_hi);

        // renormalization bookkeeping
        float s = v_lo + v_hi;
#pragma unroll
        for (int m = 16; m >= 1; m >>= 1)
            s += __shfl_xor_sync(0xffffffffu, s, m);

        C += pend;
        pend  = __logf(s);
        inv_s = __fdividef(1.0f, s);

        __syncwarp();                 // all reads of alphaS done
        alphaS[lane]      = v_lo;
        alphaS[lane + 32] = v_hi;
        __syncwarp();                 // stores visible before next read
    }

    // logZ = C + log( sum_i v[i] * exp(trans[i,63]) )   (C excludes the last pend)
    float z = v_lo * T_lo + v_hi * T_hi;
#pragma unroll
    for (int m = 16; m >= 1; m >>= 1)
        z += __shfl_xor_sync(0xffffffffu, z, m);
    float logZ = C + __logf(z);

    // gold path score
    float gold = 0.0f;
    const int* refb = ref + (size_t)b * T;
    for (int t = lane; t < S; t += 32) {
        int rt = refb[t];
        gold += prow[(size_t)t * 62 + rt];                 // emission
        int rp = (t == 0) ? 62 : refb[t - 1];              // start row at t=0 (-10000)
        gold += trans[rp * 64 + rt];                       // transition
    }
    if (lane == 0)
        gold += trans[refb[S - 1] * 64 + 63];              // final -> end
#pragma unroll
    for (int m = 16; m >= 1; m >>= 1)
        gold += __shfl_xor_sync(0xffffffffu, gold, m);

    if (lane == 0 && b < 4096)
        g_loss[b] = logZ - gold;
}

// ---------- kernel 2: deterministic fixed-order reduction ----------
__global__ void __launch_bounds__(256) crf_reduce(float* __restrict__ out, int B) {
    __shared__ double sh[256];
    double acc = 0.0;
    for (int i = threadIdx.x; i < B; i += 256)
        acc += (double)g_loss[i];
    sh[threadIdx.x] = acc;
    __syncthreads();
    for (int st = 128; st >= 1; st >>= 1) {
        if (threadIdx.x < st) sh[threadIdx.x] += sh[threadIdx.x + st];
        __syncthreads();
    }
    if (threadIdx.x == 0) out[0] = (float)sh[0];
}

extern "C" void kernel_launch(void* const* d_in, const int* in_sizes, int n_in,
                              void* d_out, int out_size) {
    const float* pred   = (const float*)d_in[0];
    const int*   ref    = (const int*)d_in[1];
    const int*   seqlen = (const int*)d_in[2];
    const float* trans  = (const float*)d_in[3];

    int B = in_sizes[2];            // 1024
    int T = in_sizes[1] / B;        // 512

    crf_precompute<<<16, 128>>>(trans);
    crf_forward<<<B, 32>>>(pred, ref, seqlen, trans, B, T);
    crf_reduce<<<1, 256>>>((float*)d_out, B);
}

// round 3
// speedup vs baseline: 1.3915x; 1.3915x over previous
#include <cuda_runtime.h>
#include <cstdint>

#define NBINS 513   // seq_len values 1..512

// Scratch (no cudaMalloc allowed)
__device__ float2 g_Mpack[64 * 32];   // g_Mpack[i*32+l] = (exp(T[i][l]), exp(T[i][l+32]))
__device__ float  g_loss[4096];
__device__ int    g_hist[NBINS];
__device__ int    g_off[NBINS];
__device__ int    g_fill[NBINS];
__device__ int    g_order[4096];

// ---------- f32x2 packed math ----------
static __device__ __forceinline__ unsigned long long pack2f(float lo, float hi) {
    unsigned long long r;
    asm("mov.b64 %0, {%1, %2};" : "=l"(r) : "f"(lo), "f"(hi));
    return r;
}
static __device__ __forceinline__ void unpack2f(unsigned long long v, float& lo, float& hi) {
    asm("mov.b64 {%0, %1}, %2;" : "=f"(lo), "=f"(hi) : "l"(v));
}
static __device__ __forceinline__ unsigned long long ffma2(unsigned long long a,
                                                           unsigned long long b,
                                                           unsigned long long c) {
    unsigned long long d;
    asm("fma.rn.f32x2 %0, %1, %2, %3;" : "=l"(d) : "l"(a), "l"(b), "l"(c));
    return d;
}
static __device__ __forceinline__ unsigned long long fadd2(unsigned long long a,
                                                           unsigned long long b) {
    unsigned long long d;
    asm("add.rn.f32x2 %0, %1, %2;" : "=l"(d) : "l"(a), "l"(b));
    return d;
}
static __device__ __forceinline__ unsigned long long fmul2(unsigned long long a,
                                                           unsigned long long b) {
    unsigned long long d;
    asm("mul.rn.f32x2 %0, %1, %2;" : "=l"(d) : "l"(a), "l"(b));
    return d;
}

// ---------- kernel 0: exp(transitions) + zero sort scratch ----------
__global__ void __launch_bounds__(128) crf_setup(const float* __restrict__ trans) {
    int idx = blockIdx.x * blockDim.x + threadIdx.x;
    if (idx < 64 * 32) {
        int i = idx >> 5, l = idx & 31;
        g_Mpack[idx] = make_float2(__expf(trans[i * 64 + l]),
                                   __expf(trans[i * 64 + l + 32]));
    }
    if (idx < NBINS) { g_hist[idx] = 0; g_fill[idx] = 0; }
}

// ---------- kernel 1: histogram of seq_len ----------
__global__ void __launch_bounds__(256) crf_hist(const int* __restrict__ seq_len, int B) {
    int b = blockIdx.x * blockDim.x + threadIdx.x;
    if (b < B) {
        int s = seq_len[b];
        if (s < 0) s = 0; if (s >= NBINS) s = NBINS - 1;
        atomicAdd(&g_hist[s], 1);
    }
}

// ---------- kernel 2: exclusive scan (descending S) ----------
__global__ void __launch_bounds__(1024) crf_scan() {
    __shared__ int sh[1024];
    int i = threadIdx.x;
    sh[i] = (i < NBINS) ? g_hist[NBINS - 1 - i] : 0;
    __syncthreads();
    for (int d = 1; d < 1024; d <<= 1) {
        int v = (i >= d) ? sh[i - d] : 0;
        __syncthreads();
        sh[i] += v;
        __syncthreads();
    }
    if (i < NBINS)
        g_off[NBINS - 1 - i] = sh[i] - g_hist[NBINS - 1 - i];  // rows with S' > S
}

// ---------- kernel 3: scatter rows into descending-S order ----------
__global__ void __launch_bounds__(256) crf_scatter(const int* __restrict__ seq_len, int B) {
    int b = blockIdx.x * blockDim.x + threadIdx.x;
    if (b < B) {
        int s = seq_len[b];
        if (s < 0) s = 0; if (s >= NBINS) s = NBINS - 1;
        int pos = g_off[s] + atomicAdd(&g_fill[s], 1);
        if (pos < 4096) g_order[pos] = b;
    }
}

// ---------- kernel 4: forward pass, 592 persistent warps ----------
__global__ void __launch_bounds__(128, 1) crf_forward(
    const float* __restrict__ pred,     // [B, T, 62]
    const int*   __restrict__ ref,      // [B, T]
    const int*   __restrict__ seq_len,  // [B]
    const float* __restrict__ trans,    // [64, 64]
    int B, int T)
{
    const int lane   = threadIdx.x & 31;
    const int warpIn = threadIdx.x >> 5;
    const int w      = blockIdx.x * 4 + warpIn;      // global warp id
    const int W      = gridDim.x * 4;                // total warps

    __shared__ __align__(16) float alphaSh[4][64];
    float* aS = alphaSh[warpIn];

    // M columns (lane, lane+32) in registers: 64 x f32x2
    unsigned long long Mreg[64];
#pragma unroll
    for (int i = 0; i < 64; i++)
        Mreg[i] = *reinterpret_cast<const unsigned long long*>(&g_Mpack[i * 32 + lane]);

    const float T_lo = g_Mpack[lane * 32 + 31].y;          // exp(trans[lane][63])
    const float T_hi = g_Mpack[(lane + 32) * 32 + 31].y;   // exp(trans[lane+32][63])

    // boustrophedon over sorted rows: balances long+short per warp
    for (int r = 0; r * W < B; r++) {
        int idx = (r & 1) ? (r * W + (W - 1 - w)) : (r * W + w);
        if (idx >= B) continue;
        const int b = g_order[idx];
        const int S = seq_len[b];
        const float* prow = pred + (size_t)b * T * 62;

        // init alpha = ones over 62 labels, C = -1000 (b_s floor)
        aS[lane]      = 1.0f;
        aS[lane + 32] = (lane < 30) ? 1.0f : 0.0f;
        __syncwarp();

        float C = -1000.0f;
        float escale = 1.0f;      // pending 1/s, folded into next chunk's first emission
        float v_lo = 1.0f, v_hi = (lane < 30) ? 1.0f : 0.0f;

        const int nch = (S + 3) >> 2;

        // triple-buffered emission prefetch (4 steps per buffer)
        float plo0[4], phi0[4], plo1[4], phi1[4], plo2[4], phi2[4];

        auto loadch = [&](float (&lo)[4], float (&hi)[4], int c) {
#pragma unroll
            for (int k = 0; k < 4; k++) {
                int u = c * 4 + k;
                if (u < S) {
                    const float* rp = prow + (size_t)u * 62;
                    lo[k] = rp[lane];
                    hi[k] = (lane < 30) ? rp[lane + 32] : 0.0f;
                } else { lo[k] = 0.0f; hi[k] = 0.0f; }
            }
        };

        loadch(plo0, phi0, 0);
        if (nch > 1) loadch(plo1, phi1, 1);

        for (int c = 0; c < nch; c++) {
            if (c + 2 < nch) loadch(plo2, phi2, c + 2);

#pragma unroll
            for (int k = 0; k < 4; k++) {
                int u = c * 4 + k;
                if (u < S) {
                    float sc = (k == 0) ? escale : 1.0f;
                    float e_lo = __expf(plo0[k]) * sc;
                    float e_hi = (lane < 30) ? __expf(phi0[k]) * sc : 0.0f;

                    // matvec: acc[j] = sum_i alpha[i]*M[i][j], 8 accumulators
                    unsigned long long a0 = 0, a1 = 0, a2 = 0, a3 = 0,
                                       a4 = 0, a5 = 0, a6 = 0, a7 = 0;
#pragma unroll
                    for (int i = 0; i < 64; i += 8) {
                        float4 x = *reinterpret_cast<const float4*>(&aS[i]);
                        float4 y = *reinterpret_cast<const float4*>(&aS[i + 4]);
                        a0 = ffma2(pack2f(x.x, x.x), Mreg[i + 0], a0);
                        a1 = ffma2(pack2f(x.y, x.y), Mreg[i + 1], a1);
                        a2 = ffma2(pack2f(x.z, x.z), Mreg[i + 2], a2);
                        a3 = ffma2(pack2f(x.w, x.w), Mreg[i + 3], a3);
                        a4 = ffma2(pack2f(y.x, y.x), Mreg[i + 4], a4);
                        a5 = ffma2(pack2f(y.y, y.y), Mreg[i + 5], a5);
                        a6 = ffma2(pack2f(y.z, y.z), Mreg[i + 6], a6);
                        a7 = ffma2(pack2f(y.w, y.w), Mreg[i + 7], a7);
                    }
                    unsigned long long acc =
                        fadd2(fadd2(fadd2(a0, a1), fadd2(a2, a3)),
                              fadd2(fadd2(a4, a5), fadd2(a6, a7)));
                    unsigned long long v2 = fmul2(acc, pack2f(e_lo, e_hi));
                    unpack2f(v2, v_lo, v_hi);

                    __syncwarp();
                    aS[lane]      = v_lo;
                    aS[lane + 32] = v_hi;
                    __syncwarp();
                }
            }

            // renormalize once per chunk (exact; lazily applied next chunk)
            if (c + 1 < nch) {
                float s = v_lo + v_hi;
#pragma unroll
                for (int m = 16; m >= 1; m >>= 1)
                    s += __shfl_xor_sync(0xffffffffu, s, m);
                C += __logf(s);
                escale = __fdividef(1.0f, s);
            }

            // rotate prefetch buffers
#pragma unroll
            for (int k = 0; k < 4; k++) {
                plo0[k] = plo1[k]; phi0[k] = phi1[k];
                plo1[k] = plo2[k]; phi1[k] = phi2[k];
            }
        }

        // logZ = C + log( sum_i v[i] * exp(trans[i,63]) )
        float z = v_lo * T_lo + v_hi * T_hi;
#pragma unroll
        for (int m = 16; m >= 1; m >>= 1)
            z += __shfl_xor_sync(0xffffffffu, z, m);
        float logZ = C + __logf(z);

        // gold path score
        float gold = 0.0f;
        const int* refb = ref + (size_t)b * T;
        for (int t = lane; t < S; t += 32) {
            int rt = refb[t];
            gold += prow[(size_t)t * 62 + rt];             // emission
            int rp = (t == 0) ? 62 : refb[t - 1];          // start row at t=0
            gold += trans[rp * 64 + rt];                   // transition
        }
        if (lane == 0)
            gold += trans[refb[S - 1] * 64 + 63];          // final -> end
#pragma unroll
        for (int m = 16; m >= 1; m >>= 1)
            gold += __shfl_xor_sync(0xffffffffu, gold, m);

        if (lane == 0 && b < 4096)
            g_loss[b] = logZ - gold;
    }
}

// ---------- kernel 5: deterministic fixed-order reduction ----------
__global__ void __launch_bounds__(256) crf_reduce(float* __restrict__ out, int B) {
    __shared__ double sh[256];
    double acc = 0.0;
    for (int i = threadIdx.x; i < B; i += 256)
        acc += (double)g_loss[i];
    sh[threadIdx.x] = acc;
    __syncthreads();
    for (int st = 128; st >= 1; st >>= 1) {
        if (threadIdx.x < st) sh[threadIdx.x] += sh[threadIdx.x + st];
        __syncthreads();
    }
    if (threadIdx.x == 0) out[0] = (float)sh[0];
}

extern "C" void kernel_launch(void* const* d_in, const int* in_sizes, int n_in,
                              void* d_out, int out_size) {
    const float* pred   = (const float*)d_in[0];
    const int*   ref    = (const int*)d_in[1];
    const int*   seqlen = (const int*)d_in[2];
    const float* trans  = (const float*)d_in[3];

    int B = in_sizes[2];            // 1024
    int T = in_sizes[1] / B;        // 512

    crf_setup<<<16, 128>>>(trans);
    crf_hist<<<(B + 255) / 256, 256>>>(seqlen, B);
    crf_scan<<<1, 1024>>>();
    crf_scatter<<<(B + 255) / 256, 256>>>(seqlen, B);
    crf_forward<<<148, 128>>>(pred, ref, seqlen, trans, B, T);
    crf_reduce<<<1, 256>>>((float*)d_out, B);
}